// round 5
// baseline (speedup 1.0000x reference)
#include <cuda_runtime.h>

// Permutation: x[B=16, C=64, H=256, W=256] fp32
//   out[b][i][j][k][cc][hh][ww] = x[b][i*32+cc][j*16+hh][k*16+ww]
//
// Round 5: double-buffered SMEM pipeline. CTA = (b, i, cc, jg); loops over 4
// consecutive j-blocks (64 KB sequential input stream). Next tile's 4 LDG.128
// are front-batched before the current tile's output phase -> loads overlap
// stores, one __syncthreads per 16 KB tile.
// SMEM rows padded 64->68 f4: conflict-free STS (input order) and LDS (output
// order) for 128-bit accesses.

static constexpr unsigned NBLOCKS = 16u * 2u * 32u * 4u;  // (b,i,cc,jg) = 4096

__global__ __launch_bounds__(256)
void reshape_78271484002964_kernel(const float4* __restrict__ in,
                                   float4* __restrict__ out) {
    __shared__ float4 sm[2][16 * 68];  // 2 x 17408 B

    unsigned bid = blockIdx.x;
    unsigned jg = bid & 3u;
    unsigned cc = (bid >> 2) & 31u;
    unsigned i  = (bid >> 7) & 1u;
    unsigned b  = bid >> 8;

    unsigned channel = (b << 6) + (i << 5) + cc;
    const float4* src = in + (channel << 14) + (jg << 12);  // jg*4 j-blocks

    unsigned t = threadIdx.x;

    // SMEM write addresses (input-linear -> padded rows), fixed per thread.
    unsigned sa0 = ((t         ) >> 6) * 68u + ((t         ) & 63u);
    unsigned sa1 = ((t +  256u ) >> 6) * 68u + ((t +  256u ) & 63u);
    unsigned sa2 = ((t +  512u ) >> 6) * 68u + ((t +  512u ) & 63u);
    unsigned sa3 = ((t +  768u ) >> 6) * 68u + ((t +  768u ) & 63u);

    // Prologue: tile 0
    float4 v0 = __ldcs(src + t);
    float4 v1 = __ldcs(src + t + 256u);
    float4 v2 = __ldcs(src + t + 512u);
    float4 v3 = __ldcs(src + t + 768u);
    sm[0][sa0] = v0; sm[0][sa1] = v1; sm[0][sa2] = v2; sm[0][sa3] = v3;
    __syncthreads();

    unsigned out_base0 = (cc << 6) + (i << 19) + (b << 20);

#pragma unroll
    for (unsigned jj = 0; jj < 4u; ++jj) {
        unsigned cur = jj & 1u;
        unsigned nxt = cur ^ 1u;

        // Front-batch next tile's loads (independent of smem state).
        if (jj < 3u) {
            const float4* s = src + ((jj + 1u) << 10);
            v0 = __ldcs(s + t);
            v1 = __ldcs(s + t + 256u);
            v2 = __ldcs(s + t + 512u);
            v3 = __ldcs(s + t + 768u);
        }

        // Output phase for current tile.
        // out f4 idx = ww4 | hh<<2 | cc<<6 | k<<11 | j<<15 | i<<19 | b<<20
        unsigned j  = (jg << 2) + jj;
        unsigned ob = out_base0 + (j << 15);
#pragma unroll
        for (unsigned it = 0; it < 4u; ++it) {
            unsigned p  = t + it * 256u;         // output-linear offset in tile
            unsigned hh = (p >> 2) & 15u;
            unsigned k  = p >> 6;
            float4 v = sm[cur][hh * 68u + (k << 2) + (p & 3u)];
            __stcs(&out[ob + (k << 11) + (p & 63u)], v);
        }

        // Stage next tile; single barrier covers both hazards:
        //  - sm[nxt] writes visible before next iteration reads them
        //  - all sm[cur] reads done before iteration jj+1 overwrites it
        if (jj < 3u) {
            sm[nxt][sa0] = v0; sm[nxt][sa1] = v1;
            sm[nxt][sa2] = v2; sm[nxt][sa3] = v3;
            __syncthreads();
        }
    }
}

extern "C" void kernel_launch(void* const* d_in, const int* in_sizes, int n_in,
                              void* d_out, int out_size) {
    const float4* in  = (const float4*)d_in[0];
    float4*       out = (float4*)d_out;

    reshape_78271484002964_kernel<<<NBLOCKS, 256>>>(in, out);
}

// round 6
// speedup vs baseline: 1.0062x; 1.0062x over previous
#include <cuda_runtime.h>

// Permutation: x[B=16, C=64, H=256, W=256] fp32
//   out[b][i][j][k][cc][hh][ww] = x[b][i*32+cc][j*16+hh][k*16+ww]
//
// Round 6: R4 structure (single 17KB smem buffer, one barrier, occ ~93%),
// but grid ordered with j in the LOW bits: consecutive CTAs read ADJACENT
// 16KB input tiles (16 CTAs = 256KB contiguous read run) for maximal DRAM
// row-buffer locality on the read stream. Writes stay 1KB-contiguous bursts.
// SMEM rows padded 64->68 f4: conflict-free 128-bit STS and LDS.

static constexpr unsigned NBLOCKS = 16u * 2u * 32u * 16u;  // (b,i,cc,j) = 16384

__global__ __launch_bounds__(256)
void reshape_78271484002964_kernel(const float4* __restrict__ in,
                                   float4* __restrict__ out) {
    __shared__ float4 sm[16 * 68];  // [hh][k*4+ww4 padded to 68] = 17408 B

    unsigned bid = blockIdx.x;
    unsigned j  = bid & 15u;          // low bits: adjacent CTAs -> adjacent reads
    unsigned cc = (bid >> 4) & 31u;
    unsigned i  = (bid >> 9) & 1u;
    unsigned b  = bid >> 10;

    unsigned channel = (b << 6) + (i << 5) + cc;
    const float4* src = in + (channel << 14) + (j << 10);

    unsigned t = threadIdx.x;

    // ---- Phase 1: stream 16 KB contiguous input (front-batched) ----
    float4 v0 = __ldcs(src + t);
    float4 v1 = __ldcs(src + t + 256u);
    float4 v2 = __ldcs(src + t + 512u);
    float4 v3 = __ldcs(src + t + 768u);

    // input-linear offset o: hh = o>>6, kw = o&63 ; smem addr = hh*68 + kw
    sm[((t        ) >> 6) * 68u + ((t        ) & 63u)] = v0;
    sm[((t + 256u ) >> 6) * 68u + ((t + 256u ) & 63u)] = v1;
    sm[((t + 512u ) >> 6) * 68u + ((t + 512u ) & 63u)] = v2;
    sm[((t + 768u ) >> 6) * 68u + ((t + 768u ) & 63u)] = v3;

    __syncthreads();

    // ---- Phase 2: emit in output order ----
    // out f4 idx = ww4 | hh<<2 | cc<<6 | k<<11 | j<<15 | i<<19 | b<<20
    unsigned out_base = (cc << 6) + (j << 15) + (i << 19) + (b << 20);

#pragma unroll
    for (unsigned it = 0; it < 4u; ++it) {
        unsigned p   = t + it * 256u;        // output-linear offset in tile
        unsigned ww4 = p & 3u;
        unsigned hh  = (p >> 2) & 15u;
        unsigned k   = p >> 6;
        float4 v = sm[hh * 68u + (k << 2) + ww4];
        __stcs(&out[out_base + (k << 11) + (p & 63u)], v);
    }
}

extern "C" void kernel_launch(void* const* d_in, const int* in_sizes, int n_in,
                              void* d_out, int out_size) {
    const float4* in  = (const float4*)d_in[0];
    float4*       out = (float4*)d_out;

    reshape_78271484002964_kernel<<<NBLOCKS, 256>>>(in, out);
}